// round 15
// baseline (speedup 1.0000x reference)
#include <cuda_runtime.h>
#include <cstdint>

// ---------------------------------------------------------------------------
// DifferentiableBiquadChain: 16 cascaded SVF biquads, per-frame coefficients.
//
// Block = (batch b, frame-pair fp) with 256 threads: half 0 (threads 0-127)
// runs frame 2fp, half 1 runs frame 2fp+1. Each half: R13 algorithm
// (uniform-hoisted affine sim + warp scan + superposition correction) with
// NAMED barriers so halves stay decoupled. State handoff 2fp -> 2fp+1 is a
// volatile SMEM slot (fast link); only odd frames publish to global g_state
// (consumed by the next block's half 0). Halves the global wavefront hops.
// ---------------------------------------------------------------------------

#define NB      16
#define FRAME   2048
#define NFR     24
#define BATCH   32
#define NFP     12
#define TPB     256
#define SPT     16
#define NW      4
#define SVAL    0xFFFFFFFFFFFFFFFFull

typedef unsigned long long ull;

__device__ ull g_state[BATCH * NFR * NB];

__global__ void init_state_kernel() {
    int i = blockIdx.x * blockDim.x + threadIdx.x;
    if (i < BATCH * NFR * NB) g_state[i] = SVAL;
}

struct M2 { float a, b, c, d; }; // [[a,b],[c,d]]

__device__ __forceinline__ M2 msq(M2 m) {
    M2 r;
    float apd = m.a + m.d;
    float bc  = m.b * m.c;
    r.a = fmaf(m.a, m.a, bc);
    r.b = m.b * apd;
    r.c = m.c * apd;
    r.d = fmaf(m.d, m.d, bc);
    return r;
}

__device__ __forceinline__ ull ld_relaxed_u64(const ull* p) {
    ull v;
    asm volatile("ld.relaxed.gpu.global.u64 %0, [%1];" : "=l"(v) : "l"(p) : "memory");
    return v;
}
__device__ __forceinline__ void st_relaxed_u64(ull* p, ull v) {
    asm volatile("st.relaxed.gpu.global.u64 [%0], %1;" : : "l"(p), "l"(v) : "memory");
}

// smem slot indices (float4 per filter)
//  0: {Aa, Ab, b1, h}
//  1: {Ac, Ad, b2, 0}
//  2: {w1, w2, 0, 0}
//  3: A^8
//  4: A^512
//  5..9:  A^16, A^32, A^64, A^128, A^256
// 10..13: {u1_j, u2_j, u1_{j+1}, u2_{j+1}} for j = 0,2,4,6

__global__ __launch_bounds__(TPB, 3)
void eq_kernel(const float* __restrict__ audio,
               const float* __restrict__ params,
               float* __restrict__ out)
{
    const int blk  = blockIdx.x;
    const int fp   = blk >> 5;    // frame pair (f-major: predecessors lower)
    const int b    = blk & 31;    // batch
    const int t    = threadIdx.x;
    const int half = t >> 7;      // 0: frame 2fp, 1: frame 2fp+1
    const int tl   = t & 127;     // thread index within half
    const int lane = t & 31;
    const int w    = tl >> 5;     // warp within half (0..3)
    const int f    = 2 * fp + half;

    __shared__ float4 um[2][NB][14];    // uniform per-filter data, per half
    __shared__ float  sh_gain[2][2];    // in_g, out_g per half
    __shared__ float  shTa[2][2][NW];   // warp totals c1 (half, double-buffer)
    __shared__ float  shTb[2][2][NW];   // warp totals c2
    __shared__ ull    sh_link[NB];      // half0 -> half1 state handoff

    // ---------------- setup: thread tl=i of each half builds filter i ----------------
    if (tl < NB) {
        const int i = tl;
        const float* pb = params + (size_t)(b * 50) * NFR + f;
        float fn = pb[(i * 3 + 0) * NFR];
        float gn = pb[(i * 3 + 1) * NFR];
        float qn = pb[(i * 3 + 2) * NFR];

        float Q = expf(fmaf(qn, 3.4657359f, -0.6931472f));
        Q = fminf(fmaxf(Q, 0.1f), 100.0f);

        float gain = fmaf(gn, 48.0f, -24.0f);
        float A  = exp10f(gain * 0.025f);   // 10^(gain/40)
        float sA = sqrtf(A);

        float lnlo, lnhi;
        if      (i == 0)            { lnlo = 2.9957323f; lnhi = 6.2146081f; } // HPF 20..500
        else if (i == 15)           { lnlo = 8.5171932f; lnhi = 9.9034876f; } // LPF 5k..20k
        else if (i == 1 || i == 14) { lnlo = 3.9120230f; lnhi = 9.6803184f; } // shelf 50..16k
        else                        { lnlo = 4.6051702f; lnhi = 9.6158055f; } // peak 100..15k
        float fc = expf(fmaf(fn, (lnhi - lnlo), lnlo));
        float g  = tanf(fc * 3.27249235e-5f);           // tan(pi*fc/96000)
        g = fminf(fmaxf(g, 1e-6f), 100.0f);

        float a1, a2, a3, m0, m1, m2;
        if (i == 0) {            // highpass
            float k = 1.0f / Q;
            a1 = 1.0f / (1.0f + g * (g + k)); a2 = g * a1; a3 = g * a2;
            m0 = 1.0f; m1 = -k; m2 = -1.0f;
        } else if (i == 15) {    // lowpass
            float k = 1.0f / Q;
            a1 = 1.0f / (1.0f + g * (g + k)); a2 = g * a1; a3 = g * a2;
            m0 = 0.0f; m1 = 0.0f; m2 = 1.0f;
        } else if (i == 1) {     // lowshelf
            float k = 1.0f / Q;
            float gs = (gain >= 0.0f) ? (g / sA) : (g * sA);
            a1 = 1.0f / (1.0f + gs * (gs + k)); a2 = gs * a1; a3 = gs * a2;
            m0 = 1.0f; m1 = k * (A - 1.0f); m2 = A * A - 1.0f;
        } else if (i == 14) {    // highshelf
            float k = 1.0f / Q;
            float gs = (gain >= 0.0f) ? (g * sA) : (g / sA);
            a1 = 1.0f / (1.0f + gs * (gs + k)); a2 = gs * a1; a3 = gs * a2;
            m0 = A * A; m1 = k * (1.0f - A) * A; m2 = 1.0f - A * A;
        } else {                 // peak
            float k = (gain >= 0.0f) ? (1.0f / (Q * A)) : (A / Q);
            a1 = 1.0f / (1.0f + g * (g + k)); a2 = g * a1; a3 = g * a2;
            m0 = 1.0f; m1 = k * (A * A - 1.0f); m2 = 0.0f;
        }

        // affine sim form: s' = Am*s + bv*x,  y = h*x + w . s
        M2 Am;
        Am.a = fmaf(2.0f, a1, -1.0f);
        Am.b = -2.0f * a2;
        Am.c = 2.0f * a1 * a2;
        Am.d = 1.0f - 2.0f * fmaf(a2, a2, a3);
        float aa  = a2 * a2 + a3;
        float b1v = 2.0f * a2;
        float b2v = 2.0f * aa;
        float h   = fmaf(m1, a2, fmaf(m2, aa, m0));
        float w1  = a1 * fmaf(m2, a2, m1);
        float w2  = fmaf(m2, 1.0f - a3 - a2 * a2, -(m1 * a2));

        M2 A8  = msq(msq(msq(Am)));
        M2 M0  = msq(A8);        // A^16
        M2 M1  = msq(M0);
        M2 M2m = msq(M1);
        M2 M3  = msq(M2m);
        M2 M4  = msq(M3);
        M2 A512 = msq(M4);

        um[half][i][0] = make_float4(Am.a, Am.b, b1v, h);
        um[half][i][1] = make_float4(Am.c, Am.d, b2v, 0.0f);
        um[half][i][2] = make_float4(w1, w2, 0.0f, 0.0f);
        um[half][i][3] = make_float4(A8.a, A8.b, A8.c, A8.d);
        um[half][i][4] = make_float4(A512.a, A512.b, A512.c, A512.d);
        um[half][i][5] = make_float4(M0.a, M0.b, M0.c, M0.d);
        um[half][i][6] = make_float4(M1.a, M1.b, M1.c, M1.d);
        um[half][i][7] = make_float4(M2m.a, M2m.b, M2m.c, M2m.d);
        um[half][i][8] = make_float4(M3.a, M3.b, M3.c, M3.d);
        um[half][i][9] = make_float4(M4.a, M4.b, M4.c, M4.d);

        // superposition rows u_j = w . A^j, j = 0..7 (pairs per float4)
        float u1 = w1, u2 = w2;
        #pragma unroll
        for (int j = 0; j < 4; j++) {
            float p1 = u1, p2 = u2;
            float q1 = fmaf(u1, Am.a, u2 * Am.c);
            float q2 = fmaf(u1, Am.b, u2 * Am.d);
            um[half][i][10 + j] = make_float4(p1, p2, q1, q2);
            u1 = fmaf(q1, Am.a, q2 * Am.c);
            u2 = fmaf(q1, Am.b, q2 * Am.d);
        }
    } else if (tl == 16 || tl == 17) {
        float n  = params[(size_t)(b * 50 + 48 + (tl - 16)) * NFR + f];
        float db = fmaf(n, 60.0f, -60.0f);
        sh_gain[half][tl - 16] = exp10f(db * 0.05f);  // 10^(db/20)
    }
    if (t >= 32 && t < 32 + NB) sh_link[t - 32] = SVAL;   // half-0 threads
    __syncthreads();   // one block-wide barrier; halves decoupled afterward

    // ---------------- load audio (x stays in registers) ----------------
    const float ing  = sh_gain[half][0];
    const float outg = sh_gain[half][1];
    float x[SPT];
    {
        const float4* ap = (const float4*)(audio + (size_t)b * 49152 + f * FRAME + tl * SPT);
        #pragma unroll
        for (int j = 0; j < 4; j++) {
            float4 v = ap[j];
            x[4 * j + 0] = v.x * ing;
            x[4 * j + 1] = v.y * ing;
            x[4 * j + 2] = v.z * ing;
            x[4 * j + 3] = v.w * ing;
        }
    }

    // links: half0 reads global (frame 2fp-1), publishes to sh_link.
    //        half1 reads sh_link,              publishes to global (frame 2fp+1).
    const ull* src_g = (half == 0 && fp > 0)
                     ? &g_state[((size_t)b * NFR + (2 * fp - 1)) * NB] : nullptr;
    ull* dst_g = (half == 1 && f < NFR - 1)
               ? &g_state[((size_t)b * NFR + f) * NB] : nullptr;
    volatile ull* link = sh_link;

    // ---------------- filter cascade ----------------
    for (int i = 0; i < NB; i++) {
        const int buf = i & 1;

        // prefetch predecessor state (hidden under sim+scan)
        ull v;
        if (half == 0) v = (src_g != nullptr) ? ld_relaxed_u64(src_g + i) : 0ull;
        else           v = link[i];

        const float4 U0 = um[half][i][0];   // Aa Ab b1 h
        const float4 U1 = um[half][i][1];   // Ac Ad b2 -
        const float4 U2 = um[half][i][2];   // w1 w2 - -
        const float4 A8 = um[half][i][3];

        // zero-state sim in two independent 8-sample halves (affine form)
        float d01, d02, c1, c2;
        {
            float p1 = 0.0f, p2 = 0.0f, q1 = 0.0f, q2 = 0.0f;
            #pragma unroll
            for (int j = 0; j < 8; j++) {
                {
                    float xn = x[j];
                    float y  = fmaf(U0.w, xn, fmaf(U2.x, p1, U2.y * p2));
                    float n1 = fmaf(U0.x, p1, fmaf(U0.y, p2, U0.z * xn));
                    float n2 = fmaf(U1.x, p1, fmaf(U1.y, p2, U1.z * xn));
                    x[j] = y; p1 = n1; p2 = n2;
                }
                {
                    float xn = x[j + 8];
                    float y  = fmaf(U0.w, xn, fmaf(U2.x, q1, U2.y * q2));
                    float n1 = fmaf(U0.x, q1, fmaf(U0.y, q2, U0.z * xn));
                    float n2 = fmaf(U1.x, q1, fmaf(U1.y, q2, U1.z * xn));
                    x[j + 8] = y; q1 = n1; q2 = n2;
                }
            }
            d01 = p1; d02 = p2;
            c1 = fmaf(A8.x, p1, fmaf(A8.y, p2, q1));
            c2 = fmaf(A8.z, p1, fmaf(A8.w, p2, q2));
        }

        // warp affine scan with precomputed level matrices
        #pragma unroll
        for (int k = 0; k < 5; k++) {
            const float4 Mk = um[half][i][5 + k];
            float o1 = __shfl_up_sync(0xFFFFFFFFu, c1, 1 << k);
            float o2 = __shfl_up_sync(0xFFFFFFFFu, c2, 1 << k);
            if (lane >= (1 << k)) {
                c1 = fmaf(Mk.x, o1, fmaf(Mk.y, o2, c1));
                c2 = fmaf(Mk.z, o1, fmaf(Mk.w, o2, c2));
            }
        }

        // within-warp exclusive offset
        float e1 = __shfl_up_sync(0xFFFFFFFFu, c1, 1);
        float e2 = __shfl_up_sync(0xFFFFFFFFu, c2, 1);
        if (lane == 0) { e1 = 0.0f; e2 = 0.0f; }

        if (lane == 31) { shTa[half][buf][w] = c1; shTb[half][buf][w] = c2; }

        // per-half named barrier (ids 1 and 2) — halves stay decoupled
        asm volatile("bar.sync %0, %1;" : : "r"(half + 1), "r"(128) : "memory");

        // resolve predecessor state
        if (half == 0) {
            if (src_g != nullptr && v == SVAL) {
                do { __nanosleep(32); v = ld_relaxed_u64(src_g + i); } while (v == SVAL);
            }
        } else {
            while (v == SVAL) { __nanosleep(20); v = link[i]; }
        }
        const float si1 = __uint_as_float((unsigned)(v & 0xFFFFFFFFu));
        const float si2 = __uint_as_float((unsigned)(v >> 32));

        const float4 A512 = um[half][i][4];

        // thread tl==0 of each half: compute frame-out state, publish ASAP
        if (tl == 0) {
            float S1 = si1, S2 = si2;
            #pragma unroll
            for (int j = 0; j < NW; j++) {
                float n1 = fmaf(A512.x, S1, fmaf(A512.y, S2, shTa[half][buf][j]));
                float n2 = fmaf(A512.z, S1, fmaf(A512.w, S2, shTb[half][buf][j]));
                S1 = n1; S2 = n2;
            }
            ull pv = ((ull)__float_as_uint(S2) << 32) | (ull)__float_as_uint(S1);
            if (half == 0)            link[i] = pv;            // smem handoff
            else if (dst_g != nullptr) st_relaxed_u64(dst_g + i, pv);
        }

        // warp-in state: chain through earlier warps' totals (warp-uniform)
        float S1 = si1, S2 = si2;
        #pragma unroll
        for (int j = 0; j < NW - 1; j++) {
            if (j < w) {
                float n1 = fmaf(A512.x, S1, fmaf(A512.y, S2, shTa[half][buf][j]));
                float n2 = fmaf(A512.z, S1, fmaf(A512.w, S2, shTb[half][buf][j]));
                S1 = n1; S2 = n2;
            }
        }

        // per-lane propagation z = A^(16*lane) . S_w (commuting matvecs)
        #pragma unroll
        for (int k = 0; k < 5; k++) {
            if (lane & (1 << k)) {
                const float4 Mk = um[half][i][5 + k];
                float n1 = fmaf(Mk.x, S1, Mk.y * S2);
                float n2 = fmaf(Mk.z, S1, Mk.w * S2);
                S1 = n1; S2 = n2;
            }
        }

        // thread-in state = z + e
        float s1 = S1 + e1;
        float s2 = S2 + e2;

        // half-1 incoming homogeneous state t1 = A^8 * s + d0
        float t11 = fmaf(A8.x, s1, fmaf(A8.y, s2, d01));
        float t12 = fmaf(A8.z, s1, fmaf(A8.w, s2, d02));

        // superposition correction with precomputed u_j rows
        #pragma unroll
        for (int j = 0; j < 4; j++) {
            const float4 U = um[half][i][10 + j];
            x[2 * j]     = fmaf(U.x, s1,  fmaf(U.y, s2,  x[2 * j]));
            x[2 * j + 8] = fmaf(U.x, t11, fmaf(U.y, t12, x[2 * j + 8]));
            x[2 * j + 1] = fmaf(U.z, s1,  fmaf(U.w, s2,  x[2 * j + 1]));
            x[2 * j + 9] = fmaf(U.z, t11, fmaf(U.w, t12, x[2 * j + 9]));
        }
    }

    // ---------------- store output ----------------
    {
        float4* op = (float4*)(out + (size_t)b * 49152 + f * FRAME + tl * SPT);
        #pragma unroll
        for (int j = 0; j < 4; j++) {
            float4 v;
            v.x = x[4 * j + 0] * outg;
            v.y = x[4 * j + 1] * outg;
            v.z = x[4 * j + 2] * outg;
            v.w = x[4 * j + 3] * outg;
            op[j] = v;
        }
    }
}

extern "C" void kernel_launch(void* const* d_in, const int* in_sizes, int n_in,
                              void* d_out, int out_size) {
    const float* audio;
    const float* params;
    if (in_sizes[0] > in_sizes[1]) { audio = (const float*)d_in[0]; params = (const float*)d_in[1]; }
    else                           { audio = (const float*)d_in[1]; params = (const float*)d_in[0]; }
    float* out = (float*)d_out;

    init_state_kernel<<<(BATCH * NFR * NB + 255) / 256, 256>>>();
    eq_kernel<<<NFP * BATCH, TPB>>>(audio, params, out);
}

// round 17
// speedup vs baseline: 1.1678x; 1.1678x over previous
#include <cuda_runtime.h>
#include <cstdint>

// ---------------------------------------------------------------------------
// DifferentiableBiquadChain: 16 cascaded SVF biquads, per-frame coefficients.
//
// Block = (frame f, batch-pair p): 128 threads x 16 samples, each thread
// carrying TWO batches (p and p+16) packed in f32x2 (lo=p, hi=p+16).
// R13 algorithm per batch: uniform-hoisted affine sim (f32x2, covers both
// batches per op) -> half combine (A^8, f32x2) -> scalar per-batch warp
// scan (scalar shuffles, no pack/unpack) -> ONE barrier -> per-warp chain +
// per-lane propagation (scalar per batch) -> publish (thread 0, 2 words) ->
// superposition correction (f32x2). Per-batch arithmetic bit-identical to
// R13; instruction count for 2 batches ~0.7x of 2 R13 blocks.
// ---------------------------------------------------------------------------

#define NB      16
#define FRAME   2048
#define NFR     24
#define BATCH   32
#define TPB     128
#define SPT     16
#define NW      4
#define SVAL    0xFFFFFFFFFFFFFFFFull

typedef unsigned long long ull;

__device__ ull g_state[BATCH * NFR * NB];

__global__ void init_state_kernel() {
    int i = blockIdx.x * blockDim.x + threadIdx.x;
    if (i < BATCH * NFR * NB) g_state[i] = SVAL;
}

// ---- packed f32x2 helpers -------------------------------------------------
__device__ __forceinline__ ull fma2(ull a, ull b, ull c) {
    ull d; asm("fma.rn.f32x2 %0,%1,%2,%3;" : "=l"(d) : "l"(a), "l"(b), "l"(c)); return d;
}
__device__ __forceinline__ ull mul2(ull a, ull b) {
    ull d; asm("mul.rn.f32x2 %0,%1,%2;" : "=l"(d) : "l"(a), "l"(b)); return d;
}
__device__ __forceinline__ ull pack2(float lo, float hi) {
    ull r; asm("mov.b64 %0,{%1,%2};" : "=l"(r) : "f"(lo), "f"(hi)); return r;
}
__device__ __forceinline__ void unpack2(ull a, float& lo, float& hi) {
    asm("mov.b64 {%0,%1}, %2;" : "=f"(lo), "=f"(hi) : "l"(a));
}

struct M2 { float a, b, c, d; };

__device__ __forceinline__ M2 msq(M2 m) {
    M2 r;
    float apd = m.a + m.d;
    float bc  = m.b * m.c;
    r.a = fmaf(m.a, m.a, bc);
    r.b = m.b * apd;
    r.c = m.c * apd;
    r.d = fmaf(m.d, m.d, bc);
    return r;
}

__device__ __forceinline__ ull ld_relaxed_u64(const ull* p) {
    ull v;
    asm volatile("ld.relaxed.gpu.global.u64 %0, [%1];" : "=l"(v) : "l"(p) : "memory");
    return v;
}
__device__ __forceinline__ void st_relaxed_u64(ull* p, ull v) {
    asm volatile("st.relaxed.gpu.global.u64 [%0], %1;" : : "l"(p), "l"(v) : "memory");
}

// packed smem layout pk[i][..] (ull = f32x2, lo=batch p, hi=batch p+16):
//  0:Aa 1:Ab 2:Ac 3:Ad 4:b1 5:b2 6:h 7:w1 8:w2
//  12..15: A8 (a,b,c,d)
//  20+2j / 21+2j : u1_j / u2_j  (j=0..7)  [ulonglong2-aligned pairs]
#define PKW 36

__global__ __launch_bounds__(TPB, 3)
void eq_kernel(const float* __restrict__ audio,
               const float* __restrict__ params,
               float* __restrict__ out)
{
    const int blk  = blockIdx.x;
    const int f    = blk >> 4;    // frame (f-major: predecessors have lower blockIdx)
    const int p    = blk & 15;    // batch pair -> batches (p, p+16)
    const int t    = threadIdx.x;
    const int lane = t & 31;
    const int w    = t >> 5;

    __shared__ ull    pk[NB][PKW];      // packed uniforms (f32x2)
    __shared__ float4 sc[2][NB][6];     // scalar per-batch: A^16..A^256, A^512
    __shared__ ull    sh_gain[2];       // packed in_g, out_g
    __shared__ float  shTa[2][2][NW];   // warp totals c1 [batch][buf][warp]
    __shared__ float  shTb[2][2][NW];   // warp totals c2

    // ---------------- setup: threads 0..31 build per-(batch,filter) uniforms ----
    if (t < 32) {
        const int bi = t >> 4;          // 0: batch p, 1: batch p+16
        const int i  = t & 15;          // filter
        const int bb = p + bi * 16;
        const float* pb = params + (size_t)(bb * 50) * NFR + f;
        float fn = pb[(i * 3 + 0) * NFR];
        float gn = pb[(i * 3 + 1) * NFR];
        float qn = pb[(i * 3 + 2) * NFR];

        float Q = expf(fmaf(qn, 3.4657359f, -0.6931472f));
        Q = fminf(fmaxf(Q, 0.1f), 100.0f);

        float gain = fmaf(gn, 48.0f, -24.0f);
        float A  = exp10f(gain * 0.025f);   // 10^(gain/40)
        float sA = sqrtf(A);

        float lnlo, lnhi;
        if      (i == 0)            { lnlo = 2.9957323f; lnhi = 6.2146081f; } // HPF 20..500
        else if (i == 15)           { lnlo = 8.5171932f; lnhi = 9.9034876f; } // LPF 5k..20k
        else if (i == 1 || i == 14) { lnlo = 3.9120230f; lnhi = 9.6803184f; } // shelf 50..16k
        else                        { lnlo = 4.6051702f; lnhi = 9.6158055f; } // peak 100..15k
        float fc = expf(fmaf(fn, (lnhi - lnlo), lnlo));
        float g  = tanf(fc * 3.27249235e-5f);           // tan(pi*fc/96000)
        g = fminf(fmaxf(g, 1e-6f), 100.0f);

        float a1, a2, a3, m0, m1, m2;
        if (i == 0) {            // highpass
            float k = 1.0f / Q;
            a1 = 1.0f / (1.0f + g * (g + k)); a2 = g * a1; a3 = g * a2;
            m0 = 1.0f; m1 = -k; m2 = -1.0f;
        } else if (i == 15) {    // lowpass
            float k = 1.0f / Q;
            a1 = 1.0f / (1.0f + g * (g + k)); a2 = g * a1; a3 = g * a2;
            m0 = 0.0f; m1 = 0.0f; m2 = 1.0f;
        } else if (i == 1) {     // lowshelf
            float k = 1.0f / Q;
            float gs = (gain >= 0.0f) ? (g / sA) : (g * sA);
            a1 = 1.0f / (1.0f + gs * (gs + k)); a2 = gs * a1; a3 = gs * a2;
            m0 = 1.0f; m1 = k * (A - 1.0f); m2 = A * A - 1.0f;
        } else if (i == 14) {    // highshelf
            float k = 1.0f / Q;
            float gs = (gain >= 0.0f) ? (g * sA) : (g / sA);
            a1 = 1.0f / (1.0f + gs * (gs + k)); a2 = gs * a1; a3 = gs * a2;
            m0 = A * A; m1 = k * (1.0f - A) * A; m2 = 1.0f - A * A;
        } else {                 // peak
            float k = (gain >= 0.0f) ? (1.0f / (Q * A)) : (A / Q);
            a1 = 1.0f / (1.0f + g * (g + k)); a2 = g * a1; a3 = g * a2;
            m0 = 1.0f; m1 = k * (A * A - 1.0f); m2 = 0.0f;
        }

        M2 Am;
        Am.a = fmaf(2.0f, a1, -1.0f);
        Am.b = -2.0f * a2;
        Am.c = 2.0f * a1 * a2;
        Am.d = 1.0f - 2.0f * fmaf(a2, a2, a3);
        float aa  = a2 * a2 + a3;
        float b1v = 2.0f * a2;
        float b2v = 2.0f * aa;
        float h   = fmaf(m1, a2, fmaf(m2, aa, m0));
        float w1  = a1 * fmaf(m2, a2, m1);
        float w2  = fmaf(m2, 1.0f - a3 - a2 * a2, -(m1 * a2));

        M2 A8  = msq(msq(msq(Am)));
        M2 M0  = msq(A8);        // A^16
        M2 M1  = msq(M0);
        M2 M2m = msq(M1);
        M2 M3  = msq(M2m);
        M2 M4  = msq(M3);
        M2 A512 = msq(M4);

        // packed halves (lo/hi float of each ull)
        float* base = (float*)&pk[i][0];
        base[0 * 2 + bi]  = Am.a;  base[1 * 2 + bi]  = Am.b;
        base[2 * 2 + bi]  = Am.c;  base[3 * 2 + bi]  = Am.d;
        base[4 * 2 + bi]  = b1v;   base[5 * 2 + bi]  = b2v;
        base[6 * 2 + bi]  = h;     base[7 * 2 + bi]  = w1;
        base[8 * 2 + bi]  = w2;
        base[12 * 2 + bi] = A8.a;  base[13 * 2 + bi] = A8.b;
        base[14 * 2 + bi] = A8.c;  base[15 * 2 + bi] = A8.d;

        // scalar scan matrices
        sc[bi][i][0] = make_float4(M0.a, M0.b, M0.c, M0.d);
        sc[bi][i][1] = make_float4(M1.a, M1.b, M1.c, M1.d);
        sc[bi][i][2] = make_float4(M2m.a, M2m.b, M2m.c, M2m.d);
        sc[bi][i][3] = make_float4(M3.a, M3.b, M3.c, M3.d);
        sc[bi][i][4] = make_float4(M4.a, M4.b, M4.c, M4.d);
        sc[bi][i][5] = make_float4(A512.a, A512.b, A512.c, A512.d);

        // superposition rows u_j = w . A^j, j = 0..7 (packed)
        float u1 = w1, u2 = w2;
        #pragma unroll
        for (int j = 0; j < 8; j++) {
            base[(20 + 2 * j) * 2 + bi] = u1;
            base[(21 + 2 * j) * 2 + bi] = u2;
            float nu1 = fmaf(u1, Am.a, u2 * Am.c);
            float nu2 = fmaf(u1, Am.b, u2 * Am.d);
            u1 = nu1; u2 = nu2;
        }
    } else if (t < 36) {
        const int idx   = t - 32;      // 0:in-lo 1:out-lo 2:in-hi 3:out-hi
        const int bi    = idx >> 1;
        const int which = idx & 1;
        const int bb = p + bi * 16;
        float n  = params[(size_t)(bb * 50 + 48 + which) * NFR + f];
        float db = fmaf(n, 60.0f, -60.0f);
        ((float*)&sh_gain[which])[bi] = exp10f(db * 0.05f);
    }
    __syncthreads();

    // ---------------- load audio (packed, stays in registers) ----------------
    const ull ingp  = sh_gain[0];
    const ull outgp = sh_gain[1];
    ull x[SPT];
    {
        const size_t off = (size_t)f * FRAME + t * SPT;
        const float4* a0 = (const float4*)(audio + (size_t)p * 49152 + off);
        const float4* a1 = (const float4*)(audio + (size_t)(p + 16) * 49152 + off);
        #pragma unroll
        for (int j = 0; j < 4; j++) {
            float4 u = a0[j], v = a1[j];
            x[4 * j + 0] = mul2(pack2(u.x, v.x), ingp);
            x[4 * j + 1] = mul2(pack2(u.y, v.y), ingp);
            x[4 * j + 2] = mul2(pack2(u.z, v.z), ingp);
            x[4 * j + 3] = mul2(pack2(u.w, v.w), ingp);
        }
    }

    const ull* src0 = (f > 0) ? &g_state[((size_t)p * NFR + (f - 1)) * NB] : nullptr;
    const ull* src1 = (f > 0) ? &g_state[((size_t)(p + 16) * NFR + (f - 1)) * NB] : nullptr;
    ull* dst0 = (f < NFR - 1) ? &g_state[((size_t)p * NFR + f) * NB] : nullptr;
    ull* dst1 = (f < NFR - 1) ? &g_state[((size_t)(p + 16) * NFR + f) * NB] : nullptr;

    // ---------------- filter cascade ----------------
    for (int i = 0; i < NB; i++) {
        const int buf = i & 1;

        // prefetch predecessor frame states (broadcast; hidden under sim+scan)
        ull v0 = 0ull, v1 = 0ull;
        if (f > 0) { v0 = ld_relaxed_u64(src0 + i); v1 = ld_relaxed_u64(src1 + i); }

        const ull AA = pk[i][0], AB = pk[i][1], AC = pk[i][2], AD = pk[i][3];
        const ull B1 = pk[i][4], B2 = pk[i][5], Hh = pk[i][6];
        const ull W1 = pk[i][7], W2 = pk[i][8];
        const ull A8a = pk[i][12], A8b = pk[i][13], A8c = pk[i][14], A8d = pk[i][15];

        // zero-state sim in two independent 8-sample halves (f32x2 covers
        // both batches); y emitted on the fly
        ull d01, d02, c1p, c2p;
        {
            ull p1 = 0ull, p2 = 0ull, q1 = 0ull, q2 = 0ull;
            #pragma unroll
            for (int j = 0; j < 8; j++) {
                {
                    ull xn = x[j];
                    ull y  = fma2(Hh, xn, fma2(W1, p1, mul2(W2, p2)));
                    ull n1 = fma2(AA, p1, fma2(AB, p2, mul2(B1, xn)));
                    ull n2 = fma2(AC, p1, fma2(AD, p2, mul2(B2, xn)));
                    x[j] = y; p1 = n1; p2 = n2;
                }
                {
                    ull xn = x[j + 8];
                    ull y  = fma2(Hh, xn, fma2(W1, q1, mul2(W2, q2)));
                    ull n1 = fma2(AA, q1, fma2(AB, q2, mul2(B1, xn)));
                    ull n2 = fma2(AC, q1, fma2(AD, q2, mul2(B2, xn)));
                    x[j + 8] = y; q1 = n1; q2 = n2;
                }
            }
            d01 = p1; d02 = p2;
            c1p = fma2(A8a, p1, fma2(A8b, p2, q1));
            c2p = fma2(A8c, p1, fma2(A8d, p2, q2));
        }

        // unpack to scalars for the scan (scalar shuffles, no pack/unpack inside)
        float c1l, c1h, c2l, c2h;
        unpack2(c1p, c1l, c1h);
        unpack2(c2p, c2l, c2h);

        #pragma unroll
        for (int k = 0; k < 5; k++) {
            const float4 M0k = sc[0][i][k];
            const float4 M1k = sc[1][i][k];
            float o1l = __shfl_up_sync(0xFFFFFFFFu, c1l, 1 << k);
            float o2l = __shfl_up_sync(0xFFFFFFFFu, c2l, 1 << k);
            float o1h = __shfl_up_sync(0xFFFFFFFFu, c1h, 1 << k);
            float o2h = __shfl_up_sync(0xFFFFFFFFu, c2h, 1 << k);
            if (lane >= (1 << k)) {
                c1l = fmaf(M0k.x, o1l, fmaf(M0k.y, o2l, c1l));
                c2l = fmaf(M0k.z, o1l, fmaf(M0k.w, o2l, c2l));
                c1h = fmaf(M1k.x, o1h, fmaf(M1k.y, o2h, c1h));
                c2h = fmaf(M1k.z, o1h, fmaf(M1k.w, o2h, c2h));
            }
        }

        // within-warp exclusive offset
        float e1l = __shfl_up_sync(0xFFFFFFFFu, c1l, 1);
        float e2l = __shfl_up_sync(0xFFFFFFFFu, c2l, 1);
        float e1h = __shfl_up_sync(0xFFFFFFFFu, c1h, 1);
        float e2h = __shfl_up_sync(0xFFFFFFFFu, c2h, 1);
        if (lane == 0) { e1l = 0.0f; e2l = 0.0f; e1h = 0.0f; e2h = 0.0f; }

        if (lane == 31) {
            shTa[0][buf][w] = c1l; shTb[0][buf][w] = c2l;
            shTa[1][buf][w] = c1h; shTb[1][buf][w] = c2h;
        }
        __syncthreads();

        // finish the spins if the prefetch raced the predecessor
        if (f > 0) {
            if (v0 == SVAL) {
                do { __nanosleep(32); v0 = ld_relaxed_u64(src0 + i); } while (v0 == SVAL);
            }
            if (v1 == SVAL) {
                do { __nanosleep(32); v1 = ld_relaxed_u64(src1 + i); } while (v1 == SVAL);
            }
        }
        float si1l = __uint_as_float((unsigned)(v0 & 0xFFFFFFFFu));
        float si2l = __uint_as_float((unsigned)(v0 >> 32));
        float si1h = __uint_as_float((unsigned)(v1 & 0xFFFFFFFFu));
        float si2h = __uint_as_float((unsigned)(v1 >> 32));

        const float4 Z0 = sc[0][i][5];   // A^512 batch lo
        const float4 Z1 = sc[1][i][5];   // A^512 batch hi

        // thread 0: compute frame-out states, publish ASAP
        if (t == 0 && dst0 != nullptr) {
            float S1 = si1l, S2 = si2l;
            #pragma unroll
            for (int j = 0; j < NW; j++) {
                float n1 = fmaf(Z0.x, S1, fmaf(Z0.y, S2, shTa[0][buf][j]));
                float n2 = fmaf(Z0.z, S1, fmaf(Z0.w, S2, shTb[0][buf][j]));
                S1 = n1; S2 = n2;
            }
            st_relaxed_u64(dst0 + i,
                ((ull)__float_as_uint(S2) << 32) | (ull)__float_as_uint(S1));
            float T1 = si1h, T2 = si2h;
            #pragma unroll
            for (int j = 0; j < NW; j++) {
                float n1 = fmaf(Z1.x, T1, fmaf(Z1.y, T2, shTa[1][buf][j]));
                float n2 = fmaf(Z1.z, T1, fmaf(Z1.w, T2, shTb[1][buf][j]));
                T1 = n1; T2 = n2;
            }
            st_relaxed_u64(dst1 + i,
                ((ull)__float_as_uint(T2) << 32) | (ull)__float_as_uint(T1));
        }

        // warp-in state: chain through earlier warps' totals (per batch, scalar)
        float S1l = si1l, S2l = si2l, S1h = si1h, S2h = si2h;
        #pragma unroll
        for (int j = 0; j < NW - 1; j++) {
            if (j < w) {
                float n1 = fmaf(Z0.x, S1l, fmaf(Z0.y, S2l, shTa[0][buf][j]));
                float n2 = fmaf(Z0.z, S1l, fmaf(Z0.w, S2l, shTb[0][buf][j]));
                S1l = n1; S2l = n2;
                float m1 = fmaf(Z1.x, S1h, fmaf(Z1.y, S2h, shTa[1][buf][j]));
                float m2 = fmaf(Z1.z, S1h, fmaf(Z1.w, S2h, shTb[1][buf][j]));
                S1h = m1; S2h = m2;
            }
        }

        // per-lane propagation z = A^(16*lane) . S_w (commuting, per batch)
        #pragma unroll
        for (int k = 0; k < 5; k++) {
            if (lane & (1 << k)) {
                const float4 M0k = sc[0][i][k];
                const float4 M1k = sc[1][i][k];
                float n1 = fmaf(M0k.x, S1l, M0k.y * S2l);
                float n2 = fmaf(M0k.z, S1l, M0k.w * S2l);
                S1l = n1; S2l = n2;
                float m1 = fmaf(M1k.x, S1h, M1k.y * S2h);
                float m2 = fmaf(M1k.z, S1h, M1k.w * S2h);
                S1h = m1; S2h = m2;
            }
        }

        // thread-in state = z + e, repacked for the f32x2 correction
        ull s1p = pack2(S1l + e1l, S1h + e1h);
        ull s2p = pack2(S2l + e2l, S2h + e2h);

        // half-1 incoming homogeneous state t1 = A^8 * s + d0 (f32x2)
        ull t11 = fma2(A8a, s1p, fma2(A8b, s2p, d01));
        ull t12 = fma2(A8c, s1p, fma2(A8d, s2p, d02));

        // superposition correction with precomputed packed u_j rows
        #pragma unroll
        for (int j = 0; j < 8; j++) {
            const ull u1 = pk[i][20 + 2 * j];
            const ull u2 = pk[i][21 + 2 * j];
            x[j]     = fma2(u1, s1p, fma2(u2, s2p, x[j]));
            x[j + 8] = fma2(u1, t11, fma2(u2, t12, x[j + 8]));
        }
    }

    // ---------------- store output ----------------
    {
        const size_t off = (size_t)f * FRAME + t * SPT;
        float4* o0 = (float4*)(out + (size_t)p * 49152 + off);
        float4* o1 = (float4*)(out + (size_t)(p + 16) * 49152 + off);
        #pragma unroll
        for (int j = 0; j < 4; j++) {
            ull y0 = mul2(x[4 * j + 0], outgp);
            ull y1 = mul2(x[4 * j + 1], outgp);
            ull y2 = mul2(x[4 * j + 2], outgp);
            ull y3 = mul2(x[4 * j + 3], outgp);
            float4 u, v;
            unpack2(y0, u.x, v.x);
            unpack2(y1, u.y, v.y);
            unpack2(y2, u.z, v.z);
            unpack2(y3, u.w, v.w);
            o0[j] = u;
            o1[j] = v;
        }
    }
}

extern "C" void kernel_launch(void* const* d_in, const int* in_sizes, int n_in,
                              void* d_out, int out_size) {
    const float* audio;
    const float* params;
    if (in_sizes[0] > in_sizes[1]) { audio = (const float*)d_in[0]; params = (const float*)d_in[1]; }
    else                           { audio = (const float*)d_in[1]; params = (const float*)d_in[0]; }
    float* out = (float*)d_out;

    init_state_kernel<<<(BATCH * NFR * NB + 255) / 256, 256>>>();
    eq_kernel<<<NFR * 16, TPB>>>(audio, params, out);
}